// round 14
// baseline (speedup 1.0000x reference)
#include <cuda_runtime.h>
#include <cuda_fp16.h>
#include <float.h>
#include <stdint.h>

// Problem constants
#define B_   4
#define T_   4096
#define DIN  1024
#define H_   16
#define D_   64
#define M_   (B_*T_)        // 16384
#define N_   (H_*D_*2)      // 2048
#define CH   64
#define NC   (T_/CH)

// Scratch
__device__ float g_v[(size_t)B_*H_*T_*D_];    // relu(v) fp32 [b][h][t][d] 64 MB
__device__ float g_st[(size_t)B_*H_*T_];      // scores   [b][h][t]
__device__ float g_cm[B_*H_*NC];
__device__ float g_cu[B_*H_*NC];
__device__ float g_cw[B_*H_*NC*D_];
__device__ __half g_A16[(size_t)M_*DIN];      // fp16(A)           32 MB
__device__ __half g_B16[(size_t)N_*DIN];      // transposed [n][k]  4 MB

// ---------------------------------------------------------------------------
// PTX helpers (sm_80-compatible only: cp.async, ldmatrix, mma.sync)
// ---------------------------------------------------------------------------
__device__ __forceinline__ uint32_t smem_u32(const void* p) {
    return (uint32_t)__cvta_generic_to_shared(p);
}
#define CP_ASYNC16(dst, src) \
    asm volatile("cp.async.cg.shared.global [%0], [%1], 16;" :: "r"(dst), "l"(src) : "memory")
#define CP_COMMIT() asm volatile("cp.async.commit_group;" ::: "memory")
#define CP_WAIT(n)  asm volatile("cp.async.wait_group %0;" :: "n"(n) : "memory")

#define LDSM_X4(r0, r1, r2, r3, addr) \
    asm volatile("ldmatrix.sync.aligned.m8n8.x4.shared.b16 {%0,%1,%2,%3}, [%4];" \
                 : "=r"(r0), "=r"(r1), "=r"(r2), "=r"(r3) : "r"(addr))

#define MMA_16816(d, a, b) \
    asm volatile("mma.sync.aligned.m16n8k16.row.col.f32.f16.f16.f32 " \
                 "{%0,%1,%2,%3},{%4,%5,%6,%7},{%8,%9},{%0,%1,%2,%3};" \
                 : "+f"((d)[0]), "+f"((d)[1]), "+f"((d)[2]), "+f"((d)[3]) \
                 : "r"((a)[0]), "r"((a)[1]), "r"((a)[2]), "r"((a)[3]), \
                   "r"((b)[0]), "r"((b)[1]))

#define SW128(o) ((o) ^ (((o) >> 3) & 0x70))

// ---------------------------------------------------------------------------
// Conversion kernels
// ---------------------------------------------------------------------------
__global__ __launch_bounds__(256) void convA_kernel(const float* __restrict__ A)
{
    const size_t idx = (size_t)blockIdx.x * 256 + threadIdx.x;   // float4 index
    float4 a = ((const float4*)A)[idx];
    __half2* hp = (__half2*)&g_A16[idx * 4];
    hp[0] = __floats2half2_rn(a.x, a.y);
    hp[1] = __floats2half2_rn(a.z, a.w);
}

__global__ __launch_bounds__(256) void convB_kernel(const float* __restrict__ Bsrc)
{
    __shared__ float tile[32][33];
    const int tx = threadIdx.x;      // 0..31
    const int ty = threadIdx.y;      // 0..7
    const int n0 = blockIdx.x * 32;
    const int k0 = blockIdx.y * 32;
#pragma unroll
    for (int r = 0; r < 4; r++)
        tile[ty + r * 8][tx] = Bsrc[(size_t)(k0 + ty + r * 8) * N_ + n0 + tx];
    __syncthreads();
#pragma unroll
    for (int r = 0; r < 4; r++) {
        const float v = tile[tx][ty + r * 8];
        const size_t o = (size_t)(n0 + ty + r * 8) * DIN + k0 + tx;
        g_B16[o] = __float2half_rn(v);
    }
}

// ---------------------------------------------------------------------------
// HMMA GEMM: CTA 128(M) x 256(N = 2 heads), 8 warps, warp tile 64x64,
// K-step 64, 16 K-tiles. 4-stage cp.async pipeline with ONE barrier per
// tile (wait(2) -> sync -> issue load(i+3) -> compute), and kk-level
// operand double-buffering (R13 verified win).
// fp32 accumulation. Fused epilogue: relu, st = q.k, v store, chunk carries.
// ---------------------------------------------------------------------------
#define NT   16
#define STAGE_A   16384          // 128 rows * 128B
#define STAGE_B   32768          // 256 rows * 128B
#define STAGE_BYTES (STAGE_A + STAGE_B)         // 49152
#define SMEM_TOTAL (4 * STAGE_BYTES)            // 196608

__device__ __forceinline__ void load_tile(uint32_t sbase, int i, int s,
                                          int m0, int n0, int tid)
{
    const int kt = i * 64;
    const uint32_t aoff = s * STAGE_BYTES;
    const uint32_t boff = aoff + STAGE_A;
#pragma unroll
    for (int r = 0; r < 4; r++) {
        const int idx = tid + r * 256;             // 0..1023
        const int row = idx >> 3, cc = idx & 7;
        const uint64_t src = __cvta_generic_to_global(g_A16 + (size_t)(m0 + row) * DIN + kt + cc * 8);
        CP_ASYNC16(sbase + aoff + SW128(row * 128 + cc * 16), src);
    }
#pragma unroll
    for (int r = 0; r < 8; r++) {
        const int idx = tid + r * 256;             // 0..2047
        const int row = idx >> 3, cc = idx & 7;
        const uint64_t src = __cvta_generic_to_global(g_B16 + (size_t)(n0 + row) * DIN + kt + cc * 8);
        CP_ASYNC16(sbase + boff + SW128(row * 128 + cc * 16), src);
    }
    CP_COMMIT();
}

__global__ __launch_bounds__(256, 1) void gemm_mma_kernel(const float* __restrict__ q)
{
    extern __shared__ char smem[];
    const uint32_t sbase = smem_u32(smem);
    const int tid  = threadIdx.x;
    const int w    = tid >> 5;
    const int lane = tid & 31;
    const int ny = blockIdx.x;              // 0..7 (fast: A-tile reuse in L2)
    const int m0 = blockIdx.y * 128;
    const int n0 = ny * 256;
    const int wm = w >> 2;                  // 0..1
    const int wn = w & 3;                   // 0..3

    float acc[4][8][4];
#pragma unroll
    for (int mi = 0; mi < 4; mi++)
#pragma unroll
        for (int n8 = 0; n8 < 8; n8++)
#pragma unroll
            for (int c = 0; c < 4; c++) acc[mi][n8][c] = 0.f;

    // prologue: stages 0,1,2 in flight
    load_tile(sbase, 0, 0, m0, n0, tid);
    load_tile(sbase, 1, 1, m0, n0, tid);
    load_tile(sbase, 2, 2, m0, n0, tid);

    // precomputed ldmatrix lane-address components
    const int aT  = lane >> 3;                       // 0..3
    const int arow_l = ((aT & 1) << 3) + (lane & 7); // +8 rows for odd T
    const int akb_l  = (aT >> 1) << 4;               // +16B for T>=2
    const int brow_l = (((lane >> 4) & 1) << 3) + (lane & 7);
    const int bkb_l  = ((lane >> 3) & 1) << 4;

    uint32_t afr[2][4][4];
    uint32_t bfr[2][8][2];

    for (int i = 0; i < NT; i++) {
        const int rem = NT - 1 - i;
        if (rem >= 2)      CP_WAIT(2);
        else if (rem == 1) CP_WAIT(1);
        else               CP_WAIT(0);
        __syncthreads();
        // load(i+3) targets stage (i+3)&3 == (i-1)&3; its readers (tile i-1)
        // are fenced by the barrier above.
        if (i + 3 < NT) load_tile(sbase, i + 3, (i + 3) & 3, m0, n0, tid);

        const uint32_t sA = sbase + (i & 3) * STAGE_BYTES;
        const uint32_t sB = sA + STAGE_A;

        // prefetch kk=0 fragments
#pragma unroll
        for (int mi = 0; mi < 4; mi++) {
            const int row = wm * 64 + mi * 16 + arow_l;
            LDSM_X4(afr[0][mi][0], afr[0][mi][1], afr[0][mi][2], afr[0][mi][3],
                    sA + SW128(row * 128 + akb_l));
        }
#pragma unroll
        for (int np = 0; np < 4; np++) {
            const int nrow = wn * 64 + np * 16 + brow_l;
            LDSM_X4(bfr[0][np * 2][0], bfr[0][np * 2][1],
                    bfr[0][np * 2 + 1][0], bfr[0][np * 2 + 1][1],
                    sB + SW128(nrow * 128 + bkb_l));
        }

#pragma unroll
        for (int kk = 0; kk < 4; kk++) {
            const int cur = kk & 1;
            const int nxt = cur ^ 1;
            if (kk < 3) {
                const int kb = (kk + 1) * 32;
#pragma unroll
                for (int mi = 0; mi < 4; mi++) {
                    const int row = wm * 64 + mi * 16 + arow_l;
                    LDSM_X4(afr[nxt][mi][0], afr[nxt][mi][1],
                            afr[nxt][mi][2], afr[nxt][mi][3],
                            sA + SW128(row * 128 + kb + akb_l));
                }
#pragma unroll
                for (int np = 0; np < 4; np++) {
                    const int nrow = wn * 64 + np * 16 + brow_l;
                    LDSM_X4(bfr[nxt][np * 2][0], bfr[nxt][np * 2][1],
                            bfr[nxt][np * 2 + 1][0], bfr[nxt][np * 2 + 1][1],
                            sB + SW128(nrow * 128 + kb + bkb_l));
                }
            }
#pragma unroll
            for (int mi = 0; mi < 4; mi++)
#pragma unroll
                for (int n8 = 0; n8 < 8; n8++)
                    MMA_16816(acc[mi][n8], afr[cur][mi], bfr[cur][n8]);
        }
    }
    __syncthreads();   // stage smem is reused as st_buf below

    // -----------------------------------------------------------------------
    // Epilogue A: relu, write v, per-row st partials to smem.
    // Column pairing: c0/c2 = k, c1/c3 = v.  d = (wn&1)*32 + n8*4 + (lane&3).
    // Head h = ny*2 + (wn>>1).
    // -----------------------------------------------------------------------
    const int h     = ny * 2 + (wn >> 1);
    const int dbase = (wn & 1) * 32 + (lane & 3);
    float qreg[8];
#pragma unroll
    for (int n8 = 0; n8 < 8; n8++) qreg[n8] = q[h * D_ + dbase + n8 * 4];

    float* st_buf = (float*)smem;                 // [128][4] per head-pair warp slot
    float* st_tot = (float*)(smem + 2048);        // [2][128] final st per head

#pragma unroll
    for (int mi = 0; mi < 4; mi++) {
        const int rl0 = wm * 64 + mi * 16 + (lane >> 2);
        float st0 = 0.f, st1 = 0.f;
#pragma unroll
        for (int n8 = 0; n8 < 8; n8++) {
            const int d = dbase + n8 * 4;
            const float k0 = fmaxf(acc[mi][n8][0], 0.f);
            const float v0 = fmaxf(acc[mi][n8][1], 0.f);
            const float k1 = fmaxf(acc[mi][n8][2], 0.f);
            const float v1 = fmaxf(acc[mi][n8][3], 0.f);
            st0 += qreg[n8] * k0;
            st1 += qreg[n8] * k1;
            {
                const int m = m0 + rl0;
                const int b = m >> 12, t = m & 4095;
                g_v[((size_t)(b * H_ + h) * T_ + t) * D_ + d] = v0;
            }
            {
                const int m = m0 + rl0 + 8;
                const int b = m >> 12, t = m & 4095;
                g_v[((size_t)(b * H_ + h) * T_ + t) * D_ + d] = v1;
            }
        }
        st0 += __shfl_xor_sync(0xffffffffu, st0, 1);
        st0 += __shfl_xor_sync(0xffffffffu, st0, 2);
        st1 += __shfl_xor_sync(0xffffffffu, st1, 1);
        st1 += __shfl_xor_sync(0xffffffffu, st1, 2);
        if ((lane & 3) == 0) {
            st_buf[rl0 * 4 + wn]       = st0;
            st_buf[(rl0 + 8) * 4 + wn] = st1;
        }
    }
    __syncthreads();

    if (tid < 128) {
        const int m = m0 + tid;
        const int b = m >> 12, t = m & 4095;
        const float s0 = st_buf[tid * 4 + 0] + st_buf[tid * 4 + 1];
        const float s1 = st_buf[tid * 4 + 2] + st_buf[tid * 4 + 3];
        g_st[(size_t)(b * H_ + ny * 2) * T_ + t]     = s0;
        g_st[(size_t)(b * H_ + ny * 2 + 1) * T_ + t] = s1;
        st_tot[tid]       = s0;
        st_tot[128 + tid] = s1;
    }
    __syncthreads();

    // -----------------------------------------------------------------------
    // Epilogue B (fused scan phase 1): commutative combine -> order-free
    // chunk-carry reduction. Warp (wm,wn): chunk wm, head h, d-range dbase.
    // -----------------------------------------------------------------------
    {
        const int hh = wn >> 1;
        const int r  = lane >> 2;
        float mloc = -FLT_MAX;
#pragma unroll
        for (int mi = 0; mi < 4; mi++) {
            mloc = fmaxf(mloc, st_tot[hh * 128 + wm * 64 + mi * 16 + r]);
            mloc = fmaxf(mloc, st_tot[hh * 128 + wm * 64 + mi * 16 + 8 + r]);
        }
        float uloc = 0.f, wloc[8];
#pragma unroll
        for (int n8 = 0; n8 < 8; n8++) wloc[n8] = 0.f;
#pragma unroll
        for (int mi = 0; mi < 4; mi++) {
            const float s0 = st_tot[hh * 128 + wm * 64 + mi * 16 + r];
            const float s1 = st_tot[hh * 128 + wm * 64 + mi * 16 + 8 + r];
            const float e0 = __expf(s0 - mloc);
            const float e1 = __expf(s1 - mloc);
            uloc += e0 + e1;
#pragma unroll
            for (int n8 = 0; n8 < 8; n8++) {
                wloc[n8] += e0 * fmaxf(acc[mi][n8][1], 0.f)
                          + e1 * fmaxf(acc[mi][n8][3], 0.f);
            }
        }
#pragma unroll
        for (int off = 4; off <= 16; off <<= 1) {
            const float m2 = __shfl_xor_sync(0xffffffffu, mloc, off);
            const float u2 = __shfl_xor_sync(0xffffffffu, uloc, off);
            const float mn = fmaxf(mloc, m2);
            const float ea = __expf(mloc - mn);
            const float eb = __expf(m2 - mn);
            uloc = uloc * ea + u2 * eb;
#pragma unroll
            for (int n8 = 0; n8 < 8; n8++) {
                const float w2 = __shfl_xor_sync(0xffffffffu, wloc[n8], off);
                wloc[n8] = wloc[n8] * ea + w2 * eb;
            }
            mloc = mn;
        }
        const int mrow0 = m0 + wm * 64;
        const int b = mrow0 >> 12;
        const int c = (mrow0 & 4095) >> 6;
        const size_t ci = (size_t)(b * H_ + h) * NC + c;
        if (r == 0) {
#pragma unroll
            for (int n8 = 0; n8 < 8; n8++)
                g_cw[ci * D_ + dbase + n8 * 4] = wloc[n8];
            if (lane == 0 && (wn & 1) == 0) { g_cm[ci] = mloc; g_cu[ci] = uloc; }
        }
    }
}

// ---------------------------------------------------------------------------
// Phase 2: per-(b,h) block, carries staged once through smem (verified win).
// ---------------------------------------------------------------------------
__global__ __launch_bounds__(64) void scan_phase2_kernel()
{
    __shared__ float sm_m[NC], sm_u[NC], sm_w[NC][D_];
    const int bh = blockIdx.x;
    const int d  = threadIdx.x;   // 0..63

    sm_m[d] = g_cm[(size_t)bh * NC + d];
    sm_u[d] = g_cu[(size_t)bh * NC + d];
    for (int c = 0; c < NC; c++)
        sm_w[c][d] = g_cw[((size_t)bh * NC + c) * D_ + d];
    __syncthreads();

    float m = -FLT_MAX, u = 0.f, w = 0.f;
    for (int c = 0; c < NC; c++) {
        const float cm = sm_m[c];
        const float cu = sm_u[c];
        const float cw = sm_w[c][d];
        g_cw[((size_t)bh * NC + c) * D_ + d] = w;
        if (d == 0) { g_cm[(size_t)bh * NC + c] = m; g_cu[(size_t)bh * NC + c] = u; }

        const float mn = fmaxf(m, cm);
        const float ea = __expf(m - mn);
        const float eb = __expf(cm - mn);
        u = u * ea + cu * eb;
        w = w * ea + cw * eb;
        m = mn;
    }
}

// ---------------------------------------------------------------------------
// Phase 3 (NEW): one warp owns (b, chunk, d-half) and scans ALL 16 heads
// in registers, summing over heads locally -> plain stores to out.
// No atomics, no memset, no intra-block barriers. 512 independent warps;
// 16 head-streams per warp give high MLP to cover DRAM latency.
// ---------------------------------------------------------------------------
__global__ __launch_bounds__(256) void scan_phase3_kernel(float* __restrict__ out)
{
    const int gw   = (blockIdx.x * blockDim.x + threadIdx.x) >> 5;  // 0..511
    const int lane = threadIdx.x & 31;
    const int b    = gw >> 7;            // 0..3
    const int c    = (gw >> 1) & 63;     // 0..63
    const int half = gw & 1;             // 0..1
    const int d    = half * 32 + lane;

    float m[H_], u[H_], wv[H_];
#pragma unroll
    for (int h = 0; h < H_; h++) {
        const size_t ci = (size_t)(b * H_ + h) * NC + c;
        m[h]  = g_cm[ci];
        u[h]  = g_cu[ci];
        wv[h] = g_cw[ci * D_ + d];
    }

    float* op = out + ((size_t)b * T_ + c * CH) * D_ + d;

    for (int i = 0; i < CH; i++) {
        float s = 0.f;
#pragma unroll
        for (int h = 0; h < H_; h++) {
            const size_t bht = (size_t)(b * H_ + h) * T_ + c * CH + i;
            const float st = __ldg(&g_st[bht]);
            const float v  = __ldg(&g_v[bht * D_ + d]);
            const float mn = fmaxf(m[h], st);
            const float ea = __expf(m[h] - mn);
            const float eb = __expf(st - mn);
            u[h]  = u[h]  * ea + eb;
            wv[h] = wv[h] * ea + v * eb;
            m[h] = mn;
            s += wv[h] * __fdividef(1.f, u[h]);
        }
        op[i * D_] = s;
    }
}

// ---------------------------------------------------------------------------
extern "C" void kernel_launch(void* const* d_in, const int* in_sizes, int n_in,
                              void* d_out, int out_size)
{
    const float* inp = nullptr;
    const float* kvk = nullptr;
    const float* qk  = nullptr;
    for (int i = 0; i < n_in; i++) {
        if (in_sizes[i] == B_ * T_ * DIN)          inp = (const float*)d_in[i];
        else if (in_sizes[i] == DIN * H_ * D_ * 2) kvk = (const float*)d_in[i];
        else if (in_sizes[i] == H_ * D_)           qk  = (const float*)d_in[i];
    }
    float* out = (float*)d_out;

    cudaFuncSetAttribute(gemm_mma_kernel,
                         cudaFuncAttributeMaxDynamicSharedMemorySize, SMEM_TOTAL);

    convA_kernel<<<(M_ * DIN / 4) / 256, 256>>>(inp);
    convB_kernel<<<dim3(N_ / 32, DIN / 32), dim3(32, 8)>>>(kvk);

    dim3 ggrid(8, M_ / 128);
    gemm_mma_kernel<<<ggrid, 256, SMEM_TOTAL>>>(qk);

    scan_phase2_kernel<<<B_ * H_, 64>>>();
    // 512 warps: 64 blocks x 256 threads
    scan_phase3_kernel<<<64, 256>>>(out);
}

// round 16
// speedup vs baseline: 2.0148x; 2.0148x over previous
#include <cuda_runtime.h>
#include <cuda_fp16.h>
#include <float.h>
#include <stdint.h>

// Problem constants
#define B_   4
#define T_   4096
#define DIN  1024
#define H_   16
#define D_   64
#define M_   (B_*T_)        // 16384
#define N_   (H_*D_*2)      // 2048
#define CH   64
#define NC   (T_/CH)

// Scratch
__device__ float g_v[(size_t)B_*H_*T_*D_];    // relu(v) fp32 [b][h][t][d] 64 MB
__device__ float g_st[(size_t)B_*H_*T_];      // scores   [b][h][t]
__device__ float g_cm[B_*H_*NC];
__device__ float g_cu[B_*H_*NC];
__device__ float g_cw[B_*H_*NC*D_];
__device__ __half g_A16[(size_t)M_*DIN];      // fp16(A)           32 MB
__device__ __half g_B16[(size_t)N_*DIN];      // transposed [n][k]  4 MB

// ---------------------------------------------------------------------------
// PTX helpers (sm_80-compatible only: cp.async, ldmatrix, mma.sync)
// ---------------------------------------------------------------------------
__device__ __forceinline__ uint32_t smem_u32(const void* p) {
    return (uint32_t)__cvta_generic_to_shared(p);
}
#define CP_ASYNC16(dst, src) \
    asm volatile("cp.async.cg.shared.global [%0], [%1], 16;" :: "r"(dst), "l"(src) : "memory")
#define CP_COMMIT() asm volatile("cp.async.commit_group;" ::: "memory")
#define CP_WAIT(n)  asm volatile("cp.async.wait_group %0;" :: "n"(n) : "memory")

#define LDSM_X4(r0, r1, r2, r3, addr) \
    asm volatile("ldmatrix.sync.aligned.m8n8.x4.shared.b16 {%0,%1,%2,%3}, [%4];" \
                 : "=r"(r0), "=r"(r1), "=r"(r2), "=r"(r3) : "r"(addr))

#define MMA_16816(d, a, b) \
    asm volatile("mma.sync.aligned.m16n8k16.row.col.f32.f16.f16.f32 " \
                 "{%0,%1,%2,%3},{%4,%5,%6,%7},{%8,%9},{%0,%1,%2,%3};" \
                 : "+f"((d)[0]), "+f"((d)[1]), "+f"((d)[2]), "+f"((d)[3]) \
                 : "r"((a)[0]), "r"((a)[1]), "r"((a)[2]), "r"((a)[3]), \
                   "r"((b)[0]), "r"((b)[1]))

#define SW128(o) ((o) ^ (((o) >> 3) & 0x70))

// ---------------------------------------------------------------------------
// Conversion kernels
// ---------------------------------------------------------------------------
__global__ __launch_bounds__(256) void convA_kernel(const float* __restrict__ A)
{
    const size_t idx = (size_t)blockIdx.x * 256 + threadIdx.x;   // float4 index
    float4 a = ((const float4*)A)[idx];
    __half2* hp = (__half2*)&g_A16[idx * 4];
    hp[0] = __floats2half2_rn(a.x, a.y);
    hp[1] = __floats2half2_rn(a.z, a.w);
}

__global__ __launch_bounds__(256) void convB_kernel(const float* __restrict__ Bsrc)
{
    __shared__ float tile[32][33];
    const int tx = threadIdx.x;      // 0..31
    const int ty = threadIdx.y;      // 0..7
    const int n0 = blockIdx.x * 32;
    const int k0 = blockIdx.y * 32;
#pragma unroll
    for (int r = 0; r < 4; r++)
        tile[ty + r * 8][tx] = Bsrc[(size_t)(k0 + ty + r * 8) * N_ + n0 + tx];
    __syncthreads();
#pragma unroll
    for (int r = 0; r < 4; r++) {
        const float v = tile[tx][ty + r * 8];
        const size_t o = (size_t)(n0 + ty + r * 8) * DIN + k0 + tx;
        g_B16[o] = __float2half_rn(v);
    }
}

// ---------------------------------------------------------------------------
// HMMA GEMM: CTA 128(M) x 256(N = 2 heads), 8 warps, warp tile 64x64,
// K-step 64, 16 K-tiles. 4-stage cp.async pipeline with ONE barrier per
// tile (wait(2) -> sync -> issue load(i+3) -> compute), and kk-level
// operand double-buffering (R13 verified win).
// fp32 accumulation. Fused epilogue: relu, st = q.k, v store, chunk carries.
// ---------------------------------------------------------------------------
#define NT   16
#define STAGE_A   16384          // 128 rows * 128B
#define STAGE_B   32768          // 256 rows * 128B
#define STAGE_BYTES (STAGE_A + STAGE_B)         // 49152
#define SMEM_TOTAL (4 * STAGE_BYTES)            // 196608

__device__ __forceinline__ void load_tile(uint32_t sbase, int i, int s,
                                          int m0, int n0, int tid)
{
    const int kt = i * 64;
    const uint32_t aoff = s * STAGE_BYTES;
    const uint32_t boff = aoff + STAGE_A;
#pragma unroll
    for (int r = 0; r < 4; r++) {
        const int idx = tid + r * 256;             // 0..1023
        const int row = idx >> 3, cc = idx & 7;
        const uint64_t src = __cvta_generic_to_global(g_A16 + (size_t)(m0 + row) * DIN + kt + cc * 8);
        CP_ASYNC16(sbase + aoff + SW128(row * 128 + cc * 16), src);
    }
#pragma unroll
    for (int r = 0; r < 8; r++) {
        const int idx = tid + r * 256;             // 0..2047
        const int row = idx >> 3, cc = idx & 7;
        const uint64_t src = __cvta_generic_to_global(g_B16 + (size_t)(n0 + row) * DIN + kt + cc * 8);
        CP_ASYNC16(sbase + boff + SW128(row * 128 + cc * 16), src);
    }
    CP_COMMIT();
}

__global__ __launch_bounds__(256, 1) void gemm_mma_kernel(const float* __restrict__ q)
{
    extern __shared__ char smem[];
    const uint32_t sbase = smem_u32(smem);
    const int tid  = threadIdx.x;
    const int w    = tid >> 5;
    const int lane = tid & 31;
    const int ny = blockIdx.x;              // 0..7 (fast: A-tile reuse in L2)
    const int m0 = blockIdx.y * 128;
    const int n0 = ny * 256;
    const int wm = w >> 2;                  // 0..1
    const int wn = w & 3;                   // 0..3

    float acc[4][8][4];
#pragma unroll
    for (int mi = 0; mi < 4; mi++)
#pragma unroll
        for (int n8 = 0; n8 < 8; n8++)
#pragma unroll
            for (int c = 0; c < 4; c++) acc[mi][n8][c] = 0.f;

    // prologue: stages 0,1,2 in flight
    load_tile(sbase, 0, 0, m0, n0, tid);
    load_tile(sbase, 1, 1, m0, n0, tid);
    load_tile(sbase, 2, 2, m0, n0, tid);

    // precomputed ldmatrix lane-address components
    const int aT  = lane >> 3;                       // 0..3
    const int arow_l = ((aT & 1) << 3) + (lane & 7); // +8 rows for odd T
    const int akb_l  = (aT >> 1) << 4;               // +16B for T>=2
    const int brow_l = (((lane >> 4) & 1) << 3) + (lane & 7);
    const int bkb_l  = ((lane >> 3) & 1) << 4;

    uint32_t afr[2][4][4];
    uint32_t bfr[2][8][2];

    for (int i = 0; i < NT; i++) {
        const int rem = NT - 1 - i;
        if (rem >= 2)      CP_WAIT(2);
        else if (rem == 1) CP_WAIT(1);
        else               CP_WAIT(0);
        __syncthreads();
        // load(i+3) targets stage (i+3)&3 == (i-1)&3; its readers (tile i-1)
        // are fenced by the barrier above.
        if (i + 3 < NT) load_tile(sbase, i + 3, (i + 3) & 3, m0, n0, tid);

        const uint32_t sA = sbase + (i & 3) * STAGE_BYTES;
        const uint32_t sB = sA + STAGE_A;

        // prefetch kk=0 fragments
#pragma unroll
        for (int mi = 0; mi < 4; mi++) {
            const int row = wm * 64 + mi * 16 + arow_l;
            LDSM_X4(afr[0][mi][0], afr[0][mi][1], afr[0][mi][2], afr[0][mi][3],
                    sA + SW128(row * 128 + akb_l));
        }
#pragma unroll
        for (int np = 0; np < 4; np++) {
            const int nrow = wn * 64 + np * 16 + brow_l;
            LDSM_X4(bfr[0][np * 2][0], bfr[0][np * 2][1],
                    bfr[0][np * 2 + 1][0], bfr[0][np * 2 + 1][1],
                    sB + SW128(nrow * 128 + bkb_l));
        }

#pragma unroll
        for (int kk = 0; kk < 4; kk++) {
            const int cur = kk & 1;
            const int nxt = cur ^ 1;
            if (kk < 3) {
                const int kb = (kk + 1) * 32;
#pragma unroll
                for (int mi = 0; mi < 4; mi++) {
                    const int row = wm * 64 + mi * 16 + arow_l;
                    LDSM_X4(afr[nxt][mi][0], afr[nxt][mi][1],
                            afr[nxt][mi][2], afr[nxt][mi][3],
                            sA + SW128(row * 128 + kb + akb_l));
                }
#pragma unroll
                for (int np = 0; np < 4; np++) {
                    const int nrow = wn * 64 + np * 16 + brow_l;
                    LDSM_X4(bfr[nxt][np * 2][0], bfr[nxt][np * 2][1],
                            bfr[nxt][np * 2 + 1][0], bfr[nxt][np * 2 + 1][1],
                            sB + SW128(nrow * 128 + kb + bkb_l));
                }
            }
#pragma unroll
            for (int mi = 0; mi < 4; mi++)
#pragma unroll
                for (int n8 = 0; n8 < 8; n8++)
                    MMA_16816(acc[mi][n8], afr[cur][mi], bfr[cur][n8]);
        }
    }
    __syncthreads();   // stage smem is reused as st_buf below

    // -----------------------------------------------------------------------
    // Epilogue A: relu, write v, per-row st partials to smem.
    // Column pairing: c0/c2 = k, c1/c3 = v.  d = (wn&1)*32 + n8*4 + (lane&3).
    // Head h = ny*2 + (wn>>1).
    // -----------------------------------------------------------------------
    const int h     = ny * 2 + (wn >> 1);
    const int dbase = (wn & 1) * 32 + (lane & 3);
    float qreg[8];
#pragma unroll
    for (int n8 = 0; n8 < 8; n8++) qreg[n8] = q[h * D_ + dbase + n8 * 4];

    float* st_buf = (float*)smem;                 // [128][4] per head-pair warp slot
    float* st_tot = (float*)(smem + 2048);        // [2][128] final st per head

#pragma unroll
    for (int mi = 0; mi < 4; mi++) {
        const int rl0 = wm * 64 + mi * 16 + (lane >> 2);
        float st0 = 0.f, st1 = 0.f;
#pragma unroll
        for (int n8 = 0; n8 < 8; n8++) {
            const int d = dbase + n8 * 4;
            const float k0 = fmaxf(acc[mi][n8][0], 0.f);
            const float v0 = fmaxf(acc[mi][n8][1], 0.f);
            const float k1 = fmaxf(acc[mi][n8][2], 0.f);
            const float v1 = fmaxf(acc[mi][n8][3], 0.f);
            st0 += qreg[n8] * k0;
            st1 += qreg[n8] * k1;
            {
                const int m = m0 + rl0;
                const int b = m >> 12, t = m & 4095;
                g_v[((size_t)(b * H_ + h) * T_ + t) * D_ + d] = v0;
            }
            {
                const int m = m0 + rl0 + 8;
                const int b = m >> 12, t = m & 4095;
                g_v[((size_t)(b * H_ + h) * T_ + t) * D_ + d] = v1;
            }
        }
        st0 += __shfl_xor_sync(0xffffffffu, st0, 1);
        st0 += __shfl_xor_sync(0xffffffffu, st0, 2);
        st1 += __shfl_xor_sync(0xffffffffu, st1, 1);
        st1 += __shfl_xor_sync(0xffffffffu, st1, 2);
        if ((lane & 3) == 0) {
            st_buf[rl0 * 4 + wn]       = st0;
            st_buf[(rl0 + 8) * 4 + wn] = st1;
        }
    }
    __syncthreads();

    if (tid < 128) {
        const int m = m0 + tid;
        const int b = m >> 12, t = m & 4095;
        const float s0 = st_buf[tid * 4 + 0] + st_buf[tid * 4 + 1];
        const float s1 = st_buf[tid * 4 + 2] + st_buf[tid * 4 + 3];
        g_st[(size_t)(b * H_ + ny * 2) * T_ + t]     = s0;
        g_st[(size_t)(b * H_ + ny * 2 + 1) * T_ + t] = s1;
        st_tot[tid]       = s0;
        st_tot[128 + tid] = s1;
    }
    __syncthreads();

    // -----------------------------------------------------------------------
    // Epilogue B (fused scan phase 1): commutative combine -> order-free
    // chunk-carry reduction. Warp (wm,wn): chunk wm, head h, d-range dbase.
    // -----------------------------------------------------------------------
    {
        const int hh = wn >> 1;
        const int r  = lane >> 2;
        float mloc = -FLT_MAX;
#pragma unroll
        for (int mi = 0; mi < 4; mi++) {
            mloc = fmaxf(mloc, st_tot[hh * 128 + wm * 64 + mi * 16 + r]);
            mloc = fmaxf(mloc, st_tot[hh * 128 + wm * 64 + mi * 16 + 8 + r]);
        }
        float uloc = 0.f, wloc[8];
#pragma unroll
        for (int n8 = 0; n8 < 8; n8++) wloc[n8] = 0.f;
#pragma unroll
        for (int mi = 0; mi < 4; mi++) {
            const float s0 = st_tot[hh * 128 + wm * 64 + mi * 16 + r];
            const float s1 = st_tot[hh * 128 + wm * 64 + mi * 16 + 8 + r];
            const float e0 = __expf(s0 - mloc);
            const float e1 = __expf(s1 - mloc);
            uloc += e0 + e1;
#pragma unroll
            for (int n8 = 0; n8 < 8; n8++) {
                wloc[n8] += e0 * fmaxf(acc[mi][n8][1], 0.f)
                          + e1 * fmaxf(acc[mi][n8][3], 0.f);
            }
        }
#pragma unroll
        for (int off = 4; off <= 16; off <<= 1) {
            const float m2 = __shfl_xor_sync(0xffffffffu, mloc, off);
            const float u2 = __shfl_xor_sync(0xffffffffu, uloc, off);
            const float mn = fmaxf(mloc, m2);
            const float ea = __expf(mloc - mn);
            const float eb = __expf(m2 - mn);
            uloc = uloc * ea + u2 * eb;
#pragma unroll
            for (int n8 = 0; n8 < 8; n8++) {
                const float w2 = __shfl_xor_sync(0xffffffffu, wloc[n8], off);
                wloc[n8] = wloc[n8] * ea + w2 * eb;
            }
            mloc = mn;
        }
        const int mrow0 = m0 + wm * 64;
        const int b = mrow0 >> 12;
        const int c = (mrow0 & 4095) >> 6;
        const size_t ci = (size_t)(b * H_ + h) * NC + c;
        if (r == 0) {
#pragma unroll
            for (int n8 = 0; n8 < 8; n8++)
                g_cw[ci * D_ + dbase + n8 * 4] = wloc[n8];
            if (lane == 0 && (wn & 1) == 0) { g_cm[ci] = mloc; g_cu[ci] = uloc; }
        }
    }
}

// ---------------------------------------------------------------------------
// Phase 2: per-(b,h) block, carries staged once through smem (verified win).
// ---------------------------------------------------------------------------
__global__ __launch_bounds__(64) void scan_phase2_kernel()
{
    __shared__ float sm_m[NC], sm_u[NC], sm_w[NC][D_];
    const int bh = blockIdx.x;
    const int d  = threadIdx.x;   // 0..63

    sm_m[d] = g_cm[(size_t)bh * NC + d];
    sm_u[d] = g_cu[(size_t)bh * NC + d];
    for (int c = 0; c < NC; c++)
        sm_w[c][d] = g_cw[((size_t)bh * NC + c) * D_ + d];
    __syncthreads();

    float m = -FLT_MAX, u = 0.f, w = 0.f;
    for (int c = 0; c < NC; c++) {
        const float cm = sm_m[c];
        const float cu = sm_u[c];
        const float cw = sm_w[c][d];
        g_cw[((size_t)bh * NC + c) * D_ + d] = w;
        if (d == 0) { g_cm[(size_t)bh * NC + c] = m; g_cu[(size_t)bh * NC + c] = u; }

        const float mn = fmaxf(m, cm);
        const float ea = __expf(m - mn);
        const float eb = __expf(cm - mn);
        u = u * ea + cu * eb;
        w = w * ea + cw * eb;
        m = mn;
    }
}

// ---------------------------------------------------------------------------
// Phase 3: one warp per (b, head-PAIR, chunk) — 2048 warps. Two independent
// head-states per warp; partial sums combined in registers -> atomics per
// output element drop 16 -> 8, st/prefix loads halve, MLP doubles.
// ---------------------------------------------------------------------------
__global__ __launch_bounds__(256) void scan_phase3_kernel(float* __restrict__ out)
{
    const int gw   = (blockIdx.x * blockDim.x + threadIdx.x) >> 5;  // 0..2047
    const int lane = threadIdx.x & 31;
    const int c  = gw & 63;              // chunk
    const int bp = gw >> 6;              // 0..31 = b*8 + hp
    const int b  = bp >> 3;
    const int hp = bp & 7;               // head pair
    const int bh0 = b * H_ + hp * 2;
    const int bh1 = bh0 + 1;

    const size_t ci0 = (size_t)bh0 * NC + c;
    const size_t ci1 = (size_t)bh1 * NC + c;
    float m0  = g_cm[ci0], u0 = g_cu[ci0];
    float w00 = g_cw[ci0 * D_ + lane];
    float w01 = g_cw[ci0 * D_ + 32 + lane];
    float m1  = g_cm[ci1], u1 = g_cu[ci1];
    float w10 = g_cw[ci1 * D_ + lane];
    float w11 = g_cw[ci1 * D_ + 32 + lane];

    const float* vp0  = g_v  + ((size_t)bh0 * T_ + c * CH) * D_;
    const float* vp1  = g_v  + ((size_t)bh1 * T_ + c * CH) * D_;
    const float* stp0 = g_st + (size_t)bh0 * T_ + c * CH;
    const float* stp1 = g_st + (size_t)bh1 * T_ + c * CH;
    float* op = out + ((size_t)b * T_ + c * CH) * D_;

    for (int i = 0; i < CH; i++) {
        const float st0 = stp0[i];
        const float st1 = stp1[i];
        const float v00 = vp0[i * D_ + lane];
        const float v01 = vp0[i * D_ + 32 + lane];
        const float v10 = vp1[i * D_ + lane];
        const float v11 = vp1[i * D_ + 32 + lane];

        {
            const float mn = fmaxf(m0, st0);
            const float ea = __expf(m0 - mn);
            const float eb = __expf(st0 - mn);
            u0  = u0  * ea + eb;
            w00 = w00 * ea + v00 * eb;
            w01 = w01 * ea + v01 * eb;
            m0 = mn;
        }
        {
            const float mn = fmaxf(m1, st1);
            const float ea = __expf(m1 - mn);
            const float eb = __expf(st1 - mn);
            u1  = u1  * ea + eb;
            w10 = w10 * ea + v10 * eb;
            w11 = w11 * ea + v11 * eb;
            m1 = mn;
        }
        const float inv0 = __fdividef(1.f, u0);
        const float inv1 = __fdividef(1.f, u1);
        atomicAdd(&op[i * D_ + lane],      w00 * inv0 + w10 * inv1);
        atomicAdd(&op[i * D_ + 32 + lane], w01 * inv0 + w11 * inv1);
    }
}

// ---------------------------------------------------------------------------
extern "C" void kernel_launch(void* const* d_in, const int* in_sizes, int n_in,
                              void* d_out, int out_size)
{
    const float* inp = nullptr;
    const float* kvk = nullptr;
    const float* qk  = nullptr;
    for (int i = 0; i < n_in; i++) {
        if (in_sizes[i] == B_ * T_ * DIN)          inp = (const float*)d_in[i];
        else if (in_sizes[i] == DIN * H_ * D_ * 2) kvk = (const float*)d_in[i];
        else if (in_sizes[i] == H_ * D_)           qk  = (const float*)d_in[i];
    }
    float* out = (float*)d_out;

    cudaFuncSetAttribute(gemm_mma_kernel,
                         cudaFuncAttributeMaxDynamicSharedMemorySize, SMEM_TOTAL);

    cudaMemsetAsync(out, 0, (size_t)out_size * sizeof(float));

    convA_kernel<<<(M_ * DIN / 4) / 256, 256>>>(inp);
    convB_kernel<<<dim3(N_ / 32, DIN / 32), dim3(32, 8)>>>(kvk);

    dim3 ggrid(8, M_ / 128);
    gemm_mma_kernel<<<ggrid, 256, SMEM_TOTAL>>>(qk);

    scan_phase2_kernel<<<B_ * H_, 64>>>();
    // 2048 warps: 256 blocks x 256 threads
    scan_phase3_kernel<<<256, 256>>>(out);
}